// round 6
// baseline (speedup 1.0000x reference)
#include <cuda_runtime.h>
#include <math.h>

#ifndef M_PI
#define M_PI 3.14159265358979323846
#endif

#define BATCH 128
#define OUT   256
#define MB    8      // M branches
#define INS   512    // inner size
#define TI    16     // batch tile
#define TB    16     // out tile
#define KC    256    // k chunk (f32 smem)
#define KCP   (KC + 2)   // even pad -> 8B-aligned rows, conflict-free LDS.64
#define NCF   9      // poly coeffs: degree 17 odd in u (deg 8 in v=u^2)
#define KSPLIT 176   // per 256-chunk: k<176 -> MUFU tanh, k>=176 -> FMA poly

struct Coeffs { float c[NCF]; };

// scratch: S[i][b][j] = sum_k sigmoid(x[i,j,k]*W[b,j,k])
__device__ float g_S[BATCH * OUT * MB];

__device__ __forceinline__ float tanh_f32a(float t) {
    float r;
    asm("tanh.approx.f32 %0, %1;" : "=f"(r) : "f"(t));
    return r;
}

// packed f32x2 ops (Blackwell)
#define MULX2(d, a, b)    asm("mul.rn.f32x2 %0, %1, %2;" : "=l"(d) : "l"(a), "l"(b))
#define ADDX2(d, a, b)    asm("add.rn.f32x2 %0, %1, %2;" : "=l"(d) : "l"(a), "l"(b))
#define FMAX2(d, a, b, c) asm("fma.rn.f32x2 %0, %1, %2, %3;" : "=l"(d) : "l"(a), "l"(b), "l"(c))
#define PACKX2(d, lo, hi) asm("mov.b64 %0, {%1, %2};" : "=l"(d) : "r"(lo), "r"(hi))
#define UNPACKX2(lo, hi, s) asm("mov.b64 {%0, %1}, %2;" : "=r"(lo), "=r"(hi) : "l"(s))

// One CTA = (16 i x 16 b) tile of ONE branch j.
// sigmoid(xw) = 0.5 + 0.5*tanh(0.5*x*w); x prescaled by 0.5 in smem.
// Hybrid: 11/16 of k-range via MUFU tanh, 5/16 via packed-FFMA polynomial
// tanh(u) ~= u * P(u^2), u clamped to [-3,3], coeffs fitted at runtime (host).
__global__ __launch_bounds__(256) void dnm_main_kernel(
    const float* __restrict__ x,
    const float* __restrict__ w,
    Coeffs cf)
{
    __shared__ float xs[TI][KCP];
    __shared__ float ws[TB][KCP];

    const int tid = threadIdx.x;
    const int tx  = tid & 15;
    const int ty  = tid >> 4;
    const int i0  = blockIdx.x * TI;
    const int b0  = blockIdx.y * TB;
    const int j   = blockIdx.z;        // 1024 CTAs total

    // duplicate-pack poly coefficients into f32x2 registers
    unsigned long long C[NCF];
    #pragma unroll
    for (int q = 0; q < NCF; ++q) {
        unsigned cb = __float_as_uint(cf.c[q]);
        PACKX2(C[q], cb, cb);
    }

    unsigned long long accM, accP;
    {
        unsigned z = 0;
        PACKX2(accM, z, z);
        PACKX2(accP, z, z);
    }

    #pragma unroll 1
    for (int kc = 0; kc < INS; kc += KC) {
        // cooperative float4 loads; x prescaled by 0.5
        #pragma unroll
        for (int it = 0; it < (TI * KC) / (4 * 256); ++it) {
            int idx = it * 256 + tid;
            int r = idx >> 6, c = (idx & 63) << 2;
            float4 v = *(const float4*)&x[((size_t)(i0 + r) * MB + j) * INS + kc + c];
            xs[r][c + 0] = 0.5f * v.x; xs[r][c + 1] = 0.5f * v.y;
            xs[r][c + 2] = 0.5f * v.z; xs[r][c + 3] = 0.5f * v.w;
        }
        #pragma unroll
        for (int it = 0; it < (TB * KC) / (4 * 256); ++it) {
            int idx = it * 256 + tid;
            int r = idx >> 6, c = (idx & 63) << 2;
            float4 v = *(const float4*)&w[((size_t)(b0 + r) * MB + j) * INS + kc + c];
            ws[r][c + 0] = v.x; ws[r][c + 1] = v.y;
            ws[r][c + 2] = v.z; ws[r][c + 3] = v.w;
        }
        __syncthreads();

        const float* xr = &xs[tx][0];
        const float* wr = &ws[ty][0];

        // ---- MUFU segment: packed mul, scalar tanh, packed accumulate ----
        #pragma unroll 8
        for (int k = 0; k < KSPLIT; k += 2) {
            unsigned long long xv = *(const unsigned long long*)&xr[k];
            unsigned long long wv = *(const unsigned long long*)&wr[k];
            unsigned long long tv;
            MULX2(tv, xv, wv);
            unsigned t0b, t1b;
            UNPACKX2(t0b, t1b, tv);
            float h0 = tanh_f32a(__uint_as_float(t0b));
            float h1 = tanh_f32a(__uint_as_float(t1b));
            unsigned long long hp;
            PACKX2(hp, __float_as_uint(h0), __float_as_uint(h1));
            ADDX2(accM, accM, hp);
        }

        // ---- poly segment: tanh(u) ~= u*P(u^2), packed Horner on FMA pipe ----
        #pragma unroll 4
        for (int k = KSPLIT; k < KC; k += 2) {
            float2 xv = *(const float2*)&xr[k];
            float2 wv = *(const float2*)&wr[k];
            float t0 = xv.x * wv.x;
            float t1 = xv.y * wv.y;
            t0 = fminf(fmaxf(t0, -3.0f), 3.0f);   // FMNMX on alu pipe
            t1 = fminf(fmaxf(t1, -3.0f), 3.0f);
            unsigned long long tp, vp, P;
            PACKX2(tp, __float_as_uint(t0), __float_as_uint(t1));
            MULX2(vp, tp, tp);
            P = C[NCF - 1];
            #pragma unroll
            for (int q = NCF - 2; q >= 0; --q)
                FMAX2(P, P, vp, C[q]);
            FMAX2(accP, tp, P, accP);            // acc += u * P(u^2)
        }
        __syncthreads();
    }

    unsigned m0, m1, p0, p1;
    UNPACKX2(m0, m1, accM);
    UNPACKX2(p0, p1, accP);
    float tot = (__uint_as_float(m0) + __uint_as_float(m1))
              + (__uint_as_float(p0) + __uint_as_float(p1));

    // sum_k sigmoid = 0.5 * sum_k tanh + 0.5 * INS
    float S = fmaf(0.5f, tot, 0.5f * (float)INS);
    g_S[((size_t)(i0 + tx) * OUT + (b0 + ty)) * MB + j] = S;
}

// Per-row normalize with fused product-of-branches.
__global__ __launch_bounds__(OUT) void dnm_norm_kernel(float* __restrict__ out)
{
    const int i = blockIdx.x;
    const int b = threadIdx.x;

    const float* sp = &g_S[((size_t)i * OUT + b) * MB];
    float4 a = *(const float4*)sp;
    float4 c = *(const float4*)(sp + 4);
    float v = ((a.x * a.y) * (a.z * a.w)) * ((c.x * c.y) * (c.z * c.w));

    // v ~ 256^8 = 2^64 -> scale before squaring (stats are scale-invariant)
    float vs = v * 0x1p-64f;

    float s1 = vs, s2 = vs * vs;
    #pragma unroll
    for (int off = 16; off > 0; off >>= 1) {
        s1 += __shfl_xor_sync(0xffffffffu, s1, off);
        s2 += __shfl_xor_sync(0xffffffffu, s2, off);
    }
    __shared__ float r1[8], r2[8];
    if ((b & 31) == 0) { r1[b >> 5] = s1; r2[b >> 5] = s2; }
    __syncthreads();

    float total = 0.0f, sq = 0.0f;
    #pragma unroll
    for (int q = 0; q < 8; ++q) { total += r1[q]; sq += r2[q]; }

    float inv = 1.0f / total;
    float zn  = vs * inv;
    float var = (sq * inv * inv - 1.0f / 256.0f) * (1.0f / 255.0f);
    out[(size_t)i * OUT + b] = (zn - 1.0f / 256.0f) * rsqrtf(var);
}

extern "C" void kernel_launch(void* const* d_in, const int* in_sizes, int n_in,
                              void* d_out, int out_size)
{
    const float* x = (const float*)d_in[0];   // (128, 8, 512)
    const float* w = (const float*)d_in[1];   // (256, 8, 512)
    float* z = (float*)d_out;                 // (128, 256)

    // ---- host-side fit (runs at capture time; deterministic):
    // Chebyshev-node interpolation of f(v) = tanh(sqrt(v))/sqrt(v) on v in [0,9],
    // degree NCF-1 in v  ->  tanh(u) ~= u * P(u^2) for |u| <= 3.
    double vn[NCF], dd[NCF];
    for (int i = 0; i < NCF; ++i) {
        double th = M_PI * (2.0 * i + 1.0) / (2.0 * NCF);
        double v  = 4.5 * (1.0 - cos(th));
        double u  = sqrt(v);
        vn[i] = v;
        dd[i] = tanh(u) / u;
    }
    // Newton divided differences (in place)
    for (int jj = 1; jj < NCF; ++jj)
        for (int i = NCF - 1; i >= jj; --i)
            dd[i] = (dd[i] - dd[i - 1]) / (vn[i] - vn[i - jj]);
    // Newton form -> monomial coefficients
    double cm[NCF];
    for (int i = 0; i < NCF; ++i) cm[i] = 0.0;
    cm[0] = dd[NCF - 1];
    int deg = 0;
    for (int k = NCF - 2; k >= 0; --k) {
        for (int d = deg + 1; d >= 0; --d) {
            double hi = (d >= 1) ? cm[d - 1] : 0.0;
            double lo = (d <= deg) ? cm[d] : 0.0;
            cm[d] = hi - vn[k] * lo;
        }
        cm[0] += dd[k];
        ++deg;
    }
    Coeffs cf;
    for (int d = 0; d < NCF; ++d) cf.c[d] = (float)cm[d];

    dim3 grid(BATCH / TI, OUT / TB, MB);      // (8, 16, 8) = 1024 CTAs
    dnm_main_kernel<<<grid, 256>>>(x, w, cf);
    dnm_norm_kernel<<<BATCH, OUT>>>(z);
}

// round 7
// speedup vs baseline: 1.0007x; 1.0007x over previous
#include <cuda_runtime.h>
#include <math.h>

#ifndef M_PI
#define M_PI 3.14159265358979323846
#endif

#define BATCH 128
#define OUT   256
#define MB    8      // M branches
#define INS   512    // inner size
#define TI    16     // batch tile
#define TB    16     // out tile
#define KC    256    // k chunk (f32 smem)
#define KCP   (KC + 2)   // even pad -> 8B-aligned rows, conflict-free LDS.64
#define NCF   8      // poly coeffs: degree 15 odd in u (deg 7 in v=u^2)
#define KSPLIT 168   // per 256-chunk: k<168 -> MUFU tanh, k>=168 -> FMA poly

struct Coeffs { float c[NCF]; };

typedef unsigned long long u64;
union F2 { float2 f; u64 u; };

// scratch: S[i][b][j] = sum_k sigmoid(x[i,j,k]*W[b,j,k])
__device__ float g_S[BATCH * OUT * MB];

__device__ __forceinline__ float tanh_f32a(float t) {
    float r;
    asm("tanh.approx.f32 %0, %1;" : "=f"(r) : "f"(t));
    return r;
}

// packed f32x2 ops (Blackwell) — operands must live in aligned pairs;
// unions keep scalar half-accesses in the SAME pair (no pack/unpack MOVs).
#define MULX2(d, a, b)    asm("mul.rn.f32x2 %0, %1, %2;" : "=l"(d) : "l"(a), "l"(b))
#define FMAX2(d, a, b, c) asm("fma.rn.f32x2 %0, %1, %2, %3;" : "=l"(d) : "l"(a), "l"(b), "l"(c))
#define PACKX2(d, lo, hi) asm("mov.b64 %0, {%1, %2};" : "=l"(d) : "r"(lo), "r"(hi))

// One CTA = (16 i x 16 b) tile of ONE branch j.
// sigmoid(xw) = 0.5 + 0.5*tanh(0.5*x*w); x prescaled by 0.5 in smem.
// Hybrid: 168/256 of k via MUFU tanh (XU pipe), 88/256 via packed-FFMA
// polynomial tanh(u) ~= u*P(u^2), u clamped to [-3,3] (FMA+ALU pipes).
// Coefficients fitted on the host at capture time (double precision).
__global__ __launch_bounds__(256) void dnm_main_kernel(
    const float* __restrict__ x,
    const float* __restrict__ w,
    Coeffs cf)
{
    __shared__ float xs[TI][KCP];
    __shared__ float ws[TB][KCP];

    const int tid = threadIdx.x;
    const int tx  = tid & 15;
    const int ty  = tid >> 4;
    const int i0  = blockIdx.x * TI;
    const int b0  = blockIdx.y * TB;
    const int j   = blockIdx.z;        // 1024 CTAs total

    // duplicate-pack poly coefficients once (outside all loops)
    u64 C[NCF];
    #pragma unroll
    for (int q = 0; q < NCF; ++q) {
        unsigned cb = __float_as_uint(cf.c[q]);
        PACKX2(C[q], cb, cb);
    }

    float accM0 = 0.0f, accM1 = 0.0f;    // MUFU-path accumulators (scalar)
    F2 accP; accP.f = make_float2(0.0f, 0.0f);

    #pragma unroll 1
    for (int kc = 0; kc < INS; kc += KC) {
        #pragma unroll
        for (int it = 0; it < (TI * KC) / (4 * 256); ++it) {
            int idx = it * 256 + tid;
            int r = idx >> 6, c = (idx & 63) << 2;
            float4 v = *(const float4*)&x[((size_t)(i0 + r) * MB + j) * INS + kc + c];
            xs[r][c + 0] = 0.5f * v.x; xs[r][c + 1] = 0.5f * v.y;
            xs[r][c + 2] = 0.5f * v.z; xs[r][c + 3] = 0.5f * v.w;
        }
        #pragma unroll
        for (int it = 0; it < (TB * KC) / (4 * 256); ++it) {
            int idx = it * 256 + tid;
            int r = idx >> 6, c = (idx & 63) << 2;
            float4 v = *(const float4*)&w[((size_t)(b0 + r) * MB + j) * INS + kc + c];
            ws[r][c + 0] = v.x; ws[r][c + 1] = v.y;
            ws[r][c + 2] = v.z; ws[r][c + 3] = v.w;
        }
        __syncthreads();

        const float* xr = &xs[tx][0];
        const float* wr = &ws[ty][0];

        // ---- MUFU segment: packed mul, scalar tanh on pair halves ----
        #pragma unroll 12
        for (int k = 0; k < KSPLIT; k += 2) {
            F2 xv, wv, tv;
            xv.u = *(const u64*)&xr[k];
            wv.u = *(const u64*)&wr[k];
            MULX2(tv.u, xv.u, wv.u);
            accM0 += tanh_f32a(tv.f.x);   // reads pair halves in place
            accM1 += tanh_f32a(tv.f.y);
        }

        // ---- poly segment: all work stays in pair registers ----
        #pragma unroll 11
        for (int k = KSPLIT; k < KC; k += 2) {
            F2 xv, wv, t, v, P;
            xv.u = *(const u64*)&xr[k];
            wv.u = *(const u64*)&wr[k];
            MULX2(t.u, xv.u, wv.u);
            t.f.x = fminf(fmaxf(t.f.x, -3.0f), 3.0f);  // scalar FMNMX, in place
            t.f.y = fminf(fmaxf(t.f.y, -3.0f), 3.0f);
            MULX2(v.u, t.u, t.u);
            P.u = C[NCF - 1];
            #pragma unroll
            for (int q = NCF - 2; q >= 0; --q)
                FMAX2(P.u, P.u, v.u, C[q]);
            FMAX2(accP.u, t.u, P.u, accP.u);           // acc += u * P(u^2)
        }
        __syncthreads();
    }

    float tot = (accM0 + accM1) + (accP.f.x + accP.f.y);

    // sum_k sigmoid = 0.5 * sum_k tanh + 0.5 * INS
    float S = fmaf(0.5f, tot, 0.5f * (float)INS);
    g_S[((size_t)(i0 + tx) * OUT + (b0 + ty)) * MB + j] = S;
}

// Per-row normalize with fused product-of-branches.
__global__ __launch_bounds__(OUT) void dnm_norm_kernel(float* __restrict__ out)
{
    const int i = blockIdx.x;
    const int b = threadIdx.x;

    const float* sp = &g_S[((size_t)i * OUT + b) * MB];
    float4 a = *(const float4*)sp;
    float4 c = *(const float4*)(sp + 4);
    float v = ((a.x * a.y) * (a.z * a.w)) * ((c.x * c.y) * (c.z * c.w));

    // v ~ 256^8 = 2^64 -> scale before squaring (stats are scale-invariant)
    float vs = v * 0x1p-64f;

    float s1 = vs, s2 = vs * vs;
    #pragma unroll
    for (int off = 16; off > 0; off >>= 1) {
        s1 += __shfl_xor_sync(0xffffffffu, s1, off);
        s2 += __shfl_xor_sync(0xffffffffu, s2, off);
    }
    __shared__ float r1[8], r2[8];
    if ((b & 31) == 0) { r1[b >> 5] = s1; r2[b >> 5] = s2; }
    __syncthreads();

    float total = 0.0f, sq = 0.0f;
    #pragma unroll
    for (int q = 0; q < 8; ++q) { total += r1[q]; sq += r2[q]; }

    float inv = 1.0f / total;
    float zn  = vs * inv;
    float var = (sq * inv * inv - 1.0f / 256.0f) * (1.0f / 255.0f);
    out[(size_t)i * OUT + b] = (zn - 1.0f / 256.0f) * rsqrtf(var);
}

extern "C" void kernel_launch(void* const* d_in, const int* in_sizes, int n_in,
                              void* d_out, int out_size)
{
    const float* x = (const float*)d_in[0];   // (128, 8, 512)
    const float* w = (const float*)d_in[1];   // (256, 8, 512)
    float* z = (float*)d_out;                 // (128, 256)

    // host-side Chebyshev-node interpolation of f(v) = tanh(sqrt(v))/sqrt(v)
    // on v in [0,9], degree NCF-1  ->  tanh(u) ~= u * P(u^2) for |u| <= 3.
    double vn[NCF], dd[NCF];
    for (int i = 0; i < NCF; ++i) {
        double th = M_PI * (2.0 * i + 1.0) / (2.0 * NCF);
        double v  = 4.5 * (1.0 - cos(th));
        double u  = sqrt(v);
        vn[i] = v;
        dd[i] = tanh(u) / u;
    }
    for (int jj = 1; jj < NCF; ++jj)
        for (int i = NCF - 1; i >= jj; --i)
            dd[i] = (dd[i] - dd[i - 1]) / (vn[i] - vn[i - jj]);
    double cm[NCF];
    for (int i = 0; i < NCF; ++i) cm[i] = 0.0;
    cm[0] = dd[NCF - 1];
    int deg = 0;
    for (int k = NCF - 2; k >= 0; --k) {
        for (int d = deg + 1; d >= 0; --d) {
            double hi = (d >= 1) ? cm[d - 1] : 0.0;
            double lo = (d <= deg) ? cm[d] : 0.0;
            cm[d] = hi - vn[k] * lo;
        }
        cm[0] += dd[k];
        ++deg;
    }
    Coeffs cf;
    for (int d = 0; d < NCF; ++d) cf.c[d] = (float)cm[d];

    dim3 grid(BATCH / TI, OUT / TB, MB);      // (8, 16, 8) = 1024 CTAs
    dnm_main_kernel<<<grid, 256>>>(x, w, cf);
    dnm_norm_kernel<<<BATCH, OUT>>>(z);
}

// round 8
// speedup vs baseline: 1.1039x; 1.1031x over previous
#include <cuda_runtime.h>
#include <cuda_fp16.h>
#include <math.h>

#define BATCH 128
#define OUT   256
#define MB    8      // M branches
#define INS   512    // inner size (full K in smem, f16)
#define TI    16     // batch tile
#define TB    16     // out tile
#define KP    (INS + 8)
#define NGRP  (BATCH / TI)   // 8 i0-groups
#define CPG   ((OUT / TB) * MB)  // 128 CTAs per group

// scratch: S[i][b][j] = sum_k sigmoid(x[i,j,k]*W[b,j,k])
__device__ float g_S[BATCH * OUT * MB];
__device__ int   g_cnt[NGRP];   // zero-init; self-resetting each launch

__device__ __forceinline__ __half2 tanh_h2(__half2 v) {
    unsigned r, a = *(unsigned*)&v;
    asm("tanh.approx.f16x2 %0, %1;" : "=r"(r) : "r"(a));
    return *(__half2*)&r;
}

// Fused: S-tile compute (r4 fast path) + last-CTA-per-group row normalize.
__global__ __launch_bounds__(256) void dnm_fused_kernel(
    const float* __restrict__ x,
    const float* __restrict__ w,
    float* __restrict__ out)
{
    __shared__ __half xs[TI][KP];
    __shared__ __half ws[TB][KP];
    __shared__ int s_last;

    const int tid = threadIdx.x;
    const int tx  = tid & 15;
    const int ty  = tid >> 4;
    const int grp = blockIdx.x;        // i0 group, 0..7
    const int i0  = grp * TI;
    const int b0  = blockIdx.y * TB;
    const int j   = blockIdx.z;        // 1024 CTAs total

    // ---- cooperative load + f32->f16 convert (x scaled by 0.5) ----
    #pragma unroll
    for (int it = 0; it < (TI * INS) / (4 * 256); ++it) {
        int idx = it * 256 + tid;
        int r = idx >> 7, c = (idx & 127) << 2;
        float4 v = *(const float4*)&x[((size_t)(i0 + r) * MB + j) * INS + c];
        *(__half2*)&xs[r][c]     = __floats2half2_rn(0.5f * v.x, 0.5f * v.y);
        *(__half2*)&xs[r][c + 2] = __floats2half2_rn(0.5f * v.z, 0.5f * v.w);
    }
    #pragma unroll
    for (int it = 0; it < (TB * INS) / (4 * 256); ++it) {
        int idx = it * 256 + tid;
        int r = idx >> 7, c = (idx & 127) << 2;
        float4 v = *(const float4*)&w[((size_t)(b0 + r) * MB + j) * INS + c];
        *(__half2*)&ws[r][c]     = __floats2half2_rn(v.x, v.y);
        *(__half2*)&ws[r][c + 2] = __floats2half2_rn(v.z, v.w);
    }
    __syncthreads();

    // ---- main loop: 4 elements / lane / iter (r4 fastest measured path) ----
    float acc0 = 0.0f, acc1 = 0.0f;
    const __half* xr = &xs[tx][0];
    const __half* wr = &ws[ty][0];

    #pragma unroll 16
    for (int k = 0; k < INS; k += 4) {
        uint2 xv = *(const uint2*)&xr[k];
        uint2 wv = *(const uint2*)&wr[k];
        __half2 t01 = __hmul2(*(__half2*)&xv.x, *(__half2*)&wv.x);
        __half2 t23 = __hmul2(*(__half2*)&xv.y, *(__half2*)&wv.y);
        __half2 h01 = tanh_h2(t01);
        __half2 h23 = tanh_h2(t23);
        __half2 s   = __hadd2(h01, h23);
        acc0 += __low2float(s);
        acc1 += __high2float(s);
    }

    float S = fmaf(0.5f, acc0 + acc1, 0.5f * (float)INS);
    g_S[((size_t)(i0 + tx) * OUT + (b0 + ty)) * MB + j] = S;

    // ---- completion protocol: last CTA of the i0-group normalizes 16 rows ----
    __threadfence();
    __syncthreads();
    if (tid == 0)
        s_last = (atomicAdd(&g_cnt[grp], 1) == CPG - 1) ? 1 : 0;
    __syncthreads();
    if (!s_last) return;

    __threadfence();   // acquire side

    // warp w -> rows i0+2w, i0+2w+1 ; lane owns b = lane + 32*q, q=0..7
    const int warp = tid >> 5;
    const int lane = tid & 31;

    #pragma unroll
    for (int rr = 0; rr < 2; ++rr) {
        const int row = i0 + 2 * warp + rr;
        float vs[8];
        float s1 = 0.0f, s2 = 0.0f;
        #pragma unroll
        for (int q = 0; q < 8; ++q) {
            int b = lane + 32 * q;
            const float4* sp = (const float4*)&g_S[((size_t)row * OUT + b) * MB];
            float4 a = __ldcg(sp);
            float4 c = __ldcg(sp + 1);
            float v = ((a.x * a.y) * (a.z * a.w)) * ((c.x * c.y) * (c.z * c.w));
            // v ~ 256^8 = 2^64 -> scale before squaring (stats scale-invariant)
            float vsc = v * 0x1p-64f;
            vs[q] = vsc;
            s1 += vsc;
            s2 += vsc * vsc;
        }
        #pragma unroll
        for (int off = 16; off > 0; off >>= 1) {
            s1 += __shfl_xor_sync(0xffffffffu, s1, off);
            s2 += __shfl_xor_sync(0xffffffffu, s2, off);
        }
        // zn = vs/total has mean exactly 1/256; ddof=1 var = (sum zn^2 - 1/256)/255
        float inv = 1.0f / s1;
        float var = (s2 * inv * inv - 1.0f / 256.0f) * (1.0f / 255.0f);
        float rstd = rsqrtf(var);
        #pragma unroll
        for (int q = 0; q < 8; ++q) {
            int b = lane + 32 * q;
            out[(size_t)row * OUT + b] = (vs[q] * inv - 1.0f / 256.0f) * rstd;
        }
    }

    if (tid == 0) g_cnt[grp] = 0;   // self-reset for next graph replay
}

extern "C" void kernel_launch(void* const* d_in, const int* in_sizes, int n_in,
                              void* d_out, int out_size)
{
    const float* x = (const float*)d_in[0];   // (128, 8, 512)
    const float* w = (const float*)d_in[1];   // (256, 8, 512)
    float* z = (float*)d_out;                 // (128, 256)

    dim3 grid(NGRP, OUT / TB, MB);            // (8, 16, 8) = 1024 CTAs
    dnm_fused_kernel<<<grid, 256>>>(x, w, z);
}